// round 11
// baseline (speedup 1.0000x reference)
#include <cuda_runtime.h>
#include <cstdint>

// Problem constants
#define N_IMG 16384
#define SS 49
#define NCELL (N_IMG * SS)              // 802816
#define F 30                            // 20 probs + 2 conf + 8 box
#define CPC 112                         // cells per chunk (= threads per block)
#define NCHUNK (NCELL / CPC)            // 7168
#define THREADS CPC
#define GRID 512                        // 7168 / 512 = 14 chunks per block, exact
#define STAGES 2

#define CHUNK_FLOATS (CPC * F)          // 3360 floats
#define CHUNK_BYTES (CHUNK_FLOATS * 4)  // 13440 B per tensor
#define TX_BYTES (2 * CHUNK_BYTES)      // 26880 B per chunk
#define DYN_SMEM (STAGES * TX_BYTES)    // 53760 B (4 blocks/SM)

#define NWARP ((THREADS + 31) / 32)     // 4 (last warp 16 lanes)

__device__ float g_partial[GRID];
__device__ unsigned int g_count;        // zero at load; last block resets each run

__device__ __forceinline__ uint32_t smem_u32(const void* p) {
    return (uint32_t)__cvta_generic_to_shared(p);
}

#define MBAR_WAIT(bar, parity) do {                                           \
    asm volatile(                                                             \
        "{\n\t.reg .pred P1;\n\t"                                             \
        "WAIT_%=:\n\t"                                                        \
        "mbarrier.try_wait.parity.acquire.cta.shared::cta.b64 P1, [%0], %1, 0x989680;\n\t" \
        "@P1 bra.uni DONE_%=;\n\t"                                            \
        "bra.uni WAIT_%=;\n\t"                                                \
        "DONE_%=:\n\t}"                                                       \
        :: "r"(bar), "r"(parity) : "memory");                                 \
} while (0)

__global__ __launch_bounds__(THREADS) void loss_kernel(
        const float* __restrict__ preds,
        const float* __restrict__ targets,
        float* __restrict__ out) {
    extern __shared__ float smem[];   // [STAGES][preds 3360 | targets 3360]
    __shared__ __align__(8) unsigned long long mbar[STAGES];
    __shared__ float warp_sums[NWARP];
    __shared__ double dsum[NWARP];
    __shared__ bool is_last;

    const int tid = threadIdx.x;

    if (tid == 0) {
#pragma unroll
        for (int s = 0; s < STAGES; s++)
            asm volatile("mbarrier.init.shared.b64 [%0], 1;"
                         :: "r"(smem_u32(&mbar[s])) : "memory");
    }
    __syncthreads();

    // Issue one chunk's loads (both tensors) into stage `buf`.
    auto issue = [&](int c, int buf) {
        uint32_t bar = smem_u32(&mbar[buf]);
        asm volatile("mbarrier.arrive.expect_tx.shared.b64 _, [%0], %1;"
                     :: "r"(bar), "r"((uint32_t)TX_BYTES) : "memory");
        uint32_t dstp = smem_u32(smem) + buf * TX_BYTES;
        uint32_t dstt = dstp + CHUNK_BYTES;
        const float* srcp = preds + (long long)c * CHUNK_FLOATS;
        const float* srct = targets + (long long)c * CHUNK_FLOATS;
        asm volatile("cp.async.bulk.shared::cta.global.mbarrier::complete_tx::bytes [%0], [%1], %2, [%3];"
                     :: "r"(dstp), "l"(srcp), "r"((uint32_t)CHUNK_BYTES), "r"(bar) : "memory");
        asm volatile("cp.async.bulk.shared::cta.global.mbarrier::complete_tx::bytes [%0], [%1], %2, [%3];"
                     :: "r"(dstt), "l"(srct), "r"((uint32_t)CHUNK_BYTES), "r"(bar) : "memory");
    };

    // Prologue: prefetch first two chunks.
    if (tid == 0) {
        issue(blockIdx.x, 0);
        issue(blockIdx.x + GRID, 1);
    }

    float l = 0.0f;
    int k = 0;
    for (int c = blockIdx.x; c < NCHUNK; c += GRID, k++) {   // exactly 14 iters/block
        const int buf = k & 1;
        const int phs = (k >> 1) & 1;
        MBAR_WAIT(smem_u32(&mbar[buf]), phs);

        const float* p = smem + buf * 2 * CHUNK_FLOATS + tid * F;
        const float* t = p + CHUNK_FLOATS;

        // conf MSE term (always): NOOBJ * sum((p_conf - t_conf)^2)
        float pc0 = p[20], pc1 = p[21];
        float tc0 = t[20], tc1 = t[21];
        float d0 = pc0 - tc0, d1 = pc1 - tc1;
        l += 0.5f * (d0 * d0 + d1 * d1);

        if (tc0 > 0.0f) {  // obj cell
            float s = 0.0f;
#pragma unroll
            for (int cc = 0; cc < 20; cc++) {
                float d = p[cc] - t[cc];
                s += d * d;
            }
            l += s;

            float iou0, iou1;
#pragma unroll
            for (int b = 0; b < 2; b++) {
                const float* pb = p + 22 + 4 * b;
                const float* tb = t + 22 + 4 * b;
                float xA = fmaxf(pb[0] - pb[2] * 0.5f, tb[0] - tb[2] * 0.5f);
                float yA = fmaxf(pb[1] - pb[3] * 0.5f, tb[1] - tb[3] * 0.5f);
                float xB = fminf(pb[0] + pb[2] * 0.5f, tb[0] + tb[2] * 0.5f);
                float yB = fminf(pb[1] + pb[3] * 0.5f, tb[1] + tb[3] * 0.5f);
                float inter = fmaxf(0.0f, xB - xA) * fmaxf(0.0f, yB - yA);
                float areaA = pb[2] * pb[3];
                float areaB = tb[2] * tb[3];
                float iou = inter / (areaA + areaB - inter);
                if (b == 0) iou0 = iou; else iou1 = iou;
            }
            int best = (iou1 > iou0) ? 1 : 0;  // argmax, tie -> index 0

            float pc = best ? pc1 : pc0;
            float dc = pc - 1.0f;
            l += 0.5f * dc * dc;

            const float* pb = p + 22 + 4 * best;
            const float* tb = t + 22 + 4 * best;
            float dx = pb[0] - tb[0];
            float dy = pb[1] - tb[1];
            float dw = sqrtf(pb[2]) - sqrtf(tb[2]);
            float dh = sqrtf(pb[3]) - sqrtf(tb[3]);
            l += 5.0f * (dx * dx + dy * dy + dw * dw + dh * dh);
        }

        __syncthreads();  // all threads done reading buffer `buf`

        int nx = c + 2 * GRID;
        if (tid == 0 && nx < NCHUNK) issue(nx, buf);
    }

    // Intra-block reduction (last warp has 16 active lanes; shfl width 32 ok:
    // inactive-lane reads return own value only for lanes >= width, so use
    // explicit 16-wide tail handling via masked shuffles).
    unsigned amask = __activemask();
#pragma unroll
    for (int off = 16; off > 0; off >>= 1) {
        float o = __shfl_down_sync(0xffffffffu, l, off);
        if ((tid & 31) + off < 32 && tid + off < THREADS) l += o;
        else if ((tid & 31) + off < 32) l += 0.0f;
        (void)amask;
    }
    if ((tid & 31) == 0)
        warp_sums[tid >> 5] = l;
    __syncthreads();

    if (tid == 0) {
        float blk = 0.0f;
#pragma unroll
        for (int w = 0; w < NWARP; w++) blk += warp_sums[w];
        g_partial[blockIdx.x] = blk;
        __threadfence();
        unsigned int old = atomicAdd(&g_count, 1u);
        is_last = (old == GRID - 1);
    }
    __syncthreads();

    if (is_last) {
        double acc = 0.0;
        for (int i = tid; i < GRID; i += THREADS)
            acc += (double)__ldcg(&g_partial[i]);
#pragma unroll
        for (int off = 16; off > 0; off >>= 1) {
            double o = __shfl_down_sync(0xffffffffu, acc, off);
            if (tid + off < THREADS && (tid & 31) + off < 32) acc += o;
        }
        if ((tid & 31) == 0)
            dsum[tid >> 5] = acc;
        __syncthreads();
        if (tid == 0) {
            double total = 0.0;
#pragma unroll
            for (int w = 0; w < NWARP; w++) total += dsum[w];
            out[0] = (float)(total / (double)N_IMG);
            __threadfence();
            g_count = 0;  // reset for next graph replay
        }
    }
}

extern "C" void kernel_launch(void* const* d_in, const int* in_sizes, int n_in,
                              void* d_out, int out_size) {
    const float* preds = (const float*)d_in[0];
    const float* targets = (const float*)d_in[1];
    float* out = (float*)d_out;

    cudaFuncSetAttribute(loss_kernel, cudaFuncAttributeMaxDynamicSharedMemorySize, DYN_SMEM);
    loss_kernel<<<GRID, THREADS, DYN_SMEM>>>(preds, targets, out);
}

// round 12
// speedup vs baseline: 1.0580x; 1.0580x over previous
#include <cuda_runtime.h>
#include <cstdint>

// Problem constants
#define N_IMG 16384
#define SS 49
#define NCELL (N_IMG * SS)              // 802816
#define F 30                            // 20 probs + 2 conf + 8 box
#define CPC 224                         // cells per chunk (= threads per block)
#define NCHUNK (NCELL / CPC)            // 3584
#define THREADS CPC                     // 224 = 7 warps
#define GRID 256                        // 3584 / 256 = 14 chunks per block, exact
#define STAGES 2

#define CHUNK_FLOATS (CPC * F)          // 6720 floats
#define CHUNK_BYTES (CHUNK_FLOATS * 4)  // 26880 B per tensor
#define TX_BYTES (2 * CHUNK_BYTES)      // 53760 B per chunk
#define DYN_SMEM (STAGES * TX_BYTES)    // 107520 B (2 blocks/SM)

#define NWARP (THREADS / 32)            // 7

__device__ float g_partial[GRID];
__device__ unsigned int g_count;        // zero at load; last block resets each run

__device__ __forceinline__ uint32_t smem_u32(const void* p) {
    return (uint32_t)__cvta_generic_to_shared(p);
}

#define MBAR_WAIT(bar, parity) do {                                           \
    asm volatile(                                                             \
        "{\n\t.reg .pred P1;\n\t"                                             \
        "WAIT_%=:\n\t"                                                        \
        "mbarrier.try_wait.parity.acquire.cta.shared::cta.b64 P1, [%0], %1, 0x989680;\n\t" \
        "@P1 bra.uni DONE_%=;\n\t"                                            \
        "bra.uni WAIT_%=;\n\t"                                                \
        "DONE_%=:\n\t}"                                                       \
        :: "r"(bar), "r"(parity) : "memory");                                 \
} while (0)

__global__ __launch_bounds__(THREADS) void loss_kernel(
        const float* __restrict__ preds,
        const float* __restrict__ targets,
        float* __restrict__ out) {
    extern __shared__ float smem[];   // [STAGES][preds 6720 | targets 6720]
    __shared__ __align__(8) unsigned long long mbar[STAGES];
    __shared__ float warp_sums[NWARP];
    __shared__ double dsum[NWARP];
    __shared__ bool is_last;

    const int tid = threadIdx.x;

    if (tid == 0) {
#pragma unroll
        for (int s = 0; s < STAGES; s++)
            asm volatile("mbarrier.init.shared.b64 [%0], 1;"
                         :: "r"(smem_u32(&mbar[s])) : "memory");
    }
    __syncthreads();

    // Issue one chunk's loads (both tensors) into stage `buf`.
    auto issue = [&](int c, int buf) {
        uint32_t bar = smem_u32(&mbar[buf]);
        asm volatile("mbarrier.arrive.expect_tx.shared.b64 _, [%0], %1;"
                     :: "r"(bar), "r"((uint32_t)TX_BYTES) : "memory");
        uint32_t dstp = smem_u32(smem) + buf * TX_BYTES;
        uint32_t dstt = dstp + CHUNK_BYTES;
        const float* srcp = preds + (long long)c * CHUNK_FLOATS;
        const float* srct = targets + (long long)c * CHUNK_FLOATS;
        asm volatile("cp.async.bulk.shared::cta.global.mbarrier::complete_tx::bytes [%0], [%1], %2, [%3];"
                     :: "r"(dstp), "l"(srcp), "r"((uint32_t)CHUNK_BYTES), "r"(bar) : "memory");
        asm volatile("cp.async.bulk.shared::cta.global.mbarrier::complete_tx::bytes [%0], [%1], %2, [%3];"
                     :: "r"(dstt), "l"(srct), "r"((uint32_t)CHUNK_BYTES), "r"(bar) : "memory");
    };

    // Prologue: prefetch first two chunks.
    if (tid == 0) {
        issue(blockIdx.x, 0);
        issue(blockIdx.x + GRID, 1);
    }

    float l = 0.0f;
    int k = 0;
    for (int c = blockIdx.x; c < NCHUNK; c += GRID, k++) {   // exactly 14 iters/block
        const int buf = k & 1;
        const int phs = (k >> 1) & 1;
        MBAR_WAIT(smem_u32(&mbar[buf]), phs);

        const float* p = smem + buf * 2 * CHUNK_FLOATS + tid * F;
        const float* t = p + CHUNK_FLOATS;

        // conf MSE term (always): NOOBJ * sum((p_conf - t_conf)^2)
        float pc0 = p[20], pc1 = p[21];
        float tc0 = t[20], tc1 = t[21];
        float d0 = pc0 - tc0, d1 = pc1 - tc1;
        l += 0.5f * (d0 * d0 + d1 * d1);

        if (tc0 > 0.0f) {  // obj cell
            float s = 0.0f;
#pragma unroll
            for (int cc = 0; cc < 20; cc++) {
                float d = p[cc] - t[cc];
                s += d * d;
            }
            l += s;

            float iou0, iou1;
#pragma unroll
            for (int b = 0; b < 2; b++) {
                const float* pb = p + 22 + 4 * b;
                const float* tb = t + 22 + 4 * b;
                float xA = fmaxf(pb[0] - pb[2] * 0.5f, tb[0] - tb[2] * 0.5f);
                float yA = fmaxf(pb[1] - pb[3] * 0.5f, tb[1] - tb[3] * 0.5f);
                float xB = fminf(pb[0] + pb[2] * 0.5f, tb[0] + tb[2] * 0.5f);
                float yB = fminf(pb[1] + pb[3] * 0.5f, tb[1] + tb[3] * 0.5f);
                float inter = fmaxf(0.0f, xB - xA) * fmaxf(0.0f, yB - yA);
                float areaA = pb[2] * pb[3];
                float areaB = tb[2] * tb[3];
                float iou = inter / (areaA + areaB - inter);
                if (b == 0) iou0 = iou; else iou1 = iou;
            }
            int best = (iou1 > iou0) ? 1 : 0;  // argmax, tie -> index 0

            float pc = best ? pc1 : pc0;
            float dc = pc - 1.0f;
            l += 0.5f * dc * dc;

            const float* pb = p + 22 + 4 * best;
            const float* tb = t + 22 + 4 * best;
            float dx = pb[0] - tb[0];
            float dy = pb[1] - tb[1];
            float dw = sqrtf(pb[2]) - sqrtf(tb[2]);
            float dh = sqrtf(pb[3]) - sqrtf(tb[3]);
            l += 5.0f * (dx * dx + dy * dy + dw * dw + dh * dh);
        }

        __syncthreads();  // all threads done reading buffer `buf`

        int nx = c + 2 * GRID;
        if (tid == 0 && nx < NCHUNK) issue(nx, buf);
    }

    // Intra-block reduction (7 full warps).
#pragma unroll
    for (int off = 16; off > 0; off >>= 1)
        l += __shfl_down_sync(0xffffffffu, l, off);
    if ((tid & 31) == 0)
        warp_sums[tid >> 5] = l;
    __syncthreads();

    if (tid == 0) {
        float blk = 0.0f;
#pragma unroll
        for (int w = 0; w < NWARP; w++) blk += warp_sums[w];
        g_partial[blockIdx.x] = blk;
        __threadfence();
        unsigned int old = atomicAdd(&g_count, 1u);
        is_last = (old == GRID - 1);
    }
    __syncthreads();

    if (is_last) {
        double acc = 0.0;
        for (int i = tid; i < GRID; i += THREADS)
            acc += (double)__ldcg(&g_partial[i]);
#pragma unroll
        for (int off = 16; off > 0; off >>= 1)
            acc += __shfl_down_sync(0xffffffffu, acc, off);
        if ((tid & 31) == 0)
            dsum[tid >> 5] = acc;
        __syncthreads();
        if (tid == 0) {
            double total = 0.0;
#pragma unroll
            for (int w = 0; w < NWARP; w++) total += dsum[w];
            out[0] = (float)(total / (double)N_IMG);
            __threadfence();
            g_count = 0;  // reset for next graph replay
        }
    }
}

extern "C" void kernel_launch(void* const* d_in, const int* in_sizes, int n_in,
                              void* d_out, int out_size) {
    const float* preds = (const float*)d_in[0];
    const float* targets = (const float*)d_in[1];
    float* out = (float*)d_out;

    cudaFuncSetAttribute(loss_kernel, cudaFuncAttributeMaxDynamicSharedMemorySize, DYN_SMEM);
    loss_kernel<<<GRID, THREADS, DYN_SMEM>>>(preds, targets, out);
}